// round 1
// baseline (speedup 1.0000x reference)
#include <cuda_runtime.h>

// Problem constants
#define Bq 2
#define Sq 2048
#define Eq 1024
#define Hq 16
#define Dq 64
#define KKq 409           // max(1, int(S*0.2))
#define SCOREMUL 0.15625f // (1/sqrt(64)) / temperature, temperature = 0.8
#define DIAGMUL  1.15f    // 1 + ACH*0.3
#define MASKMUL  1.15f    // 1 + (-DA)*0.3

// ---------------------------------------------------------------------------
// Scratch (device globals; no allocation allowed in kernel_launch)
// ---------------------------------------------------------------------------
__device__ float g_Q [Bq*Hq*Sq*Dq];   // (b,h,s,d)
__device__ float g_Kt[Bq*Hq*Dq*Sq];   // (b,h,d,s)  transposed, pre-scaled by time_scales
__device__ float g_V [Bq*Hq*Sq*Dq];   // (b,h,s,d)
__device__ float g_O [Bq*Sq*Eq];      // (b,s,e)    attention output before Wo

// ---------------------------------------------------------------------------
// Monotonic float->uint map: a >= b  <=>  fmap(a) >= fmap(b)
// ---------------------------------------------------------------------------
__device__ __forceinline__ unsigned fmap(float f) {
    unsigned u = __float_as_uint(f);
    return (u & 0x80000000u) ? ~u : (u | 0x80000000u);
}

// ---------------------------------------------------------------------------
// Projection GEMM: out(mode) = in(mode) @ W(mode) + b(mode)
// mode 0: query -> g_Q   (b,h,s,d)
// mode 1: key   -> g_Kt  (b,h,d,s), * time_scales[h]
// mode 2: value -> g_V   (b,h,s,d)
// Tiles: BM=BN=64, BK=16, 256 threads, 4x4 microtile.
// ---------------------------------------------------------------------------
__global__ __launch_bounds__(256) void proj_kernel(
    const float* __restrict__ qin, const float* __restrict__ kin, const float* __restrict__ vin,
    const float* __restrict__ Wq, const float* __restrict__ bq,
    const float* __restrict__ Wk, const float* __restrict__ bk,
    const float* __restrict__ Wv, const float* __restrict__ bv,
    const float* __restrict__ ts)
{
    const int mode = blockIdx.z;
    const float* A    = (mode == 0) ? qin : (mode == 1) ? kin : vin;
    const float* W    = (mode == 0) ? Wq  : (mode == 1) ? Wk  : Wv;
    const float* bias = (mode == 0) ? bq  : (mode == 1) ? bk  : bv;

    __shared__ float As[16][68];   // padded to reduce store conflicts
    __shared__ float Bs[16][64];

    const int tid = threadIdx.x;
    const int tx = tid & 15, ty = tid >> 4;
    const int m0 = blockIdx.y * 64, n0 = blockIdx.x * 64;

    const int aRow = tid >> 2;          // 0..63
    const int aCol = (tid & 3) << 2;    // 0,4,8,12
    const int bRow = tid >> 4;          // 0..15
    const int bCol = (tid & 15) << 2;   // 0..60

    const float* Aptr = A + (size_t)(m0 + aRow) * Eq + aCol;
    const float* Wptr = W + (size_t)bRow * Eq + n0 + bCol;

    float acc[4][4];
    #pragma unroll
    for (int i = 0; i < 4; ++i)
        #pragma unroll
        for (int j = 0; j < 4; ++j) acc[i][j] = 0.0f;

    for (int k0 = 0; k0 < Eq; k0 += 16) {
        float4 av  = *(const float4*)(Aptr + k0);
        float4 wv4 = *(const float4*)(Wptr + (size_t)k0 * Eq);
        __syncthreads();
        As[aCol + 0][aRow] = av.x;
        As[aCol + 1][aRow] = av.y;
        As[aCol + 2][aRow] = av.z;
        As[aCol + 3][aRow] = av.w;
        *(float4*)&Bs[bRow][bCol] = wv4;
        __syncthreads();
        #pragma unroll
        for (int k = 0; k < 16; ++k) {
            float a[4], bb[4];
            #pragma unroll
            for (int i = 0; i < 4; ++i) a[i]  = As[k][ty * 4 + i];
            #pragma unroll
            for (int j = 0; j < 4; ++j) bb[j] = Bs[k][tx * 4 + j];
            #pragma unroll
            for (int i = 0; i < 4; ++i)
                #pragma unroll
                for (int j = 0; j < 4; ++j)
                    acc[i][j] = fmaf(a[i], bb[j], acc[i][j]);
        }
    }

    #pragma unroll
    for (int i = 0; i < 4; ++i) {
        int r = m0 + ty * 4 + i;
        int b = r >> 11;          // / Sq
        int s = r & (Sq - 1);
        #pragma unroll
        for (int j = 0; j < 4; ++j) {
            int c = n0 + tx * 4 + j;
            int h = c >> 6, d = c & 63;
            float v = acc[i][j] + bias[c];
            if (mode == 0)
                g_Q[((size_t)(b * Hq + h) * Sq + s) * Dq + d] = v;
            else if (mode == 1)
                g_Kt[((size_t)(b * Hq + h) * Dq + d) * Sq + s] = v * ts[h];
            else
                g_V[((size_t)(b * Hq + h) * Sq + s) * Dq + d] = v;
        }
    }
}

// ---------------------------------------------------------------------------
// Output GEMM: d_out = g_O @ Wo + bo
// ---------------------------------------------------------------------------
__global__ __launch_bounds__(256) void outproj_kernel(
    const float* __restrict__ Wo, const float* __restrict__ bo,
    float* __restrict__ out)
{
    __shared__ float As[16][68];
    __shared__ float Bs[16][64];

    const int tid = threadIdx.x;
    const int tx = tid & 15, ty = tid >> 4;
    const int m0 = blockIdx.y * 64, n0 = blockIdx.x * 64;

    const int aRow = tid >> 2;
    const int aCol = (tid & 3) << 2;
    const int bRow = tid >> 4;
    const int bCol = (tid & 15) << 2;

    const float* Aptr = g_O + (size_t)(m0 + aRow) * Eq + aCol;
    const float* Wptr = Wo + (size_t)bRow * Eq + n0 + bCol;

    float acc[4][4];
    #pragma unroll
    for (int i = 0; i < 4; ++i)
        #pragma unroll
        for (int j = 0; j < 4; ++j) acc[i][j] = 0.0f;

    for (int k0 = 0; k0 < Eq; k0 += 16) {
        float4 av  = *(const float4*)(Aptr + k0);
        float4 wv4 = *(const float4*)(Wptr + (size_t)k0 * Eq);
        __syncthreads();
        As[aCol + 0][aRow] = av.x;
        As[aCol + 1][aRow] = av.y;
        As[aCol + 2][aRow] = av.z;
        As[aCol + 3][aRow] = av.w;
        *(float4*)&Bs[bRow][bCol] = wv4;
        __syncthreads();
        #pragma unroll
        for (int k = 0; k < 16; ++k) {
            float a[4], bb[4];
            #pragma unroll
            for (int i = 0; i < 4; ++i) a[i]  = As[k][ty * 4 + i];
            #pragma unroll
            for (int j = 0; j < 4; ++j) bb[j] = Bs[k][tx * 4 + j];
            #pragma unroll
            for (int i = 0; i < 4; ++i)
                #pragma unroll
                for (int j = 0; j < 4; ++j)
                    acc[i][j] = fmaf(a[i], bb[j], acc[i][j]);
        }
    }

    #pragma unroll
    for (int i = 0; i < 4; ++i) {
        int r = m0 + ty * 4 + i;
        #pragma unroll
        for (int j = 0; j < 4; ++j) {
            int c = n0 + tx * 4 + j;
            out[(size_t)r * Eq + c] = acc[i][j] + bo[c];
        }
    }
}

// ---------------------------------------------------------------------------
// Fused attention: one block per (b,h,t) row.
//   scores -> topk(409) threshold (exact, bitwise select) -> mask boost ->
//   softmax -> attn @ V
// ---------------------------------------------------------------------------
__global__ __launch_bounds__(256) void attn_kernel()
{
    __shared__ float    sc[Sq];        // scores / probabilities
    __shared__ unsigned su[Sq];        // monotonically mapped score bits
    __shared__ float    qs[Dq];
    __shared__ float    red[16 * Dq];  // partial sums for attn@V
    __shared__ float    fscr[8];
    __shared__ unsigned uscr[8];
    __shared__ unsigned bcastu;
    __shared__ float    bcastf;

    const int tid = threadIdx.x;
    const int t   = blockIdx.x;
    const int bh  = blockIdx.y;        // b*H + h
    const int b   = bh >> 4;
    const int h   = bh & 15;

    if (tid < Dq) qs[tid] = g_Q[((size_t)bh * Sq + t) * Dq + tid];
    __syncthreads();

    // ---- scores = (q . K^T) * SCOREMUL, diag boost ----
    const float4* Kt4 = (const float4*)(g_Kt + (size_t)bh * Dq * Sq);
    #pragma unroll
    for (int j = 0; j < 2; ++j) {
        int s4 = tid + j * 256;                  // float4 index, s = 4*s4
        float4 acc = make_float4(0.f, 0.f, 0.f, 0.f);
        #pragma unroll 8
        for (int d = 0; d < Dq; ++d) {
            float4 kv = Kt4[(size_t)d * (Sq / 4) + s4];
            float qd = qs[d];
            acc.x = fmaf(qd, kv.x, acc.x);
            acc.y = fmaf(qd, kv.y, acc.y);
            acc.z = fmaf(qd, kv.z, acc.z);
            acc.w = fmaf(qd, kv.w, acc.w);
        }
        int s = s4 * 4;
        float v0 = acc.x * SCOREMUL; if (s + 0 == t) v0 *= DIAGMUL;
        float v1 = acc.y * SCOREMUL; if (s + 1 == t) v1 *= DIAGMUL;
        float v2 = acc.z * SCOREMUL; if (s + 2 == t) v2 *= DIAGMUL;
        float v3 = acc.w * SCOREMUL; if (s + 3 == t) v3 *= DIAGMUL;
        sc[s + 0] = v0; su[s + 0] = fmap(v0);
        sc[s + 1] = v1; su[s + 1] = fmap(v1);
        sc[s + 2] = v2; su[s + 2] = fmap(v2);
        sc[s + 3] = v3; su[s + 3] = fmap(v3);
    }
    __syncthreads();

    // ---- exact kk-th largest via bitwise binary search on mapped bits ----
    // thr = max T such that count(su >= T) >= KK; thr equals fmap(min_topk).
    unsigned thr = 0;
    for (int bit = 31; bit >= 0; --bit) {
        unsigned cand = thr | (1u << bit);
        unsigned c = 0;
        #pragma unroll
        for (int j = 0; j < 8; ++j)
            c += (su[tid + j * 256] >= cand) ? 1u : 0u;
        #pragma unroll
        for (int o = 16; o; o >>= 1) c += __shfl_xor_sync(0xFFFFFFFFu, c, o);
        if ((tid & 31) == 0) uscr[tid >> 5] = c;
        __syncthreads();
        if (tid < 8) {
            unsigned x = uscr[tid];
            x += __shfl_xor_sync(0xFFu, x, 4);
            x += __shfl_xor_sync(0xFFu, x, 2);
            x += __shfl_xor_sync(0xFFu, x, 1);
            if (tid == 0) bcastu = x;
        }
        __syncthreads();
        if (bcastu >= KKq) thr = cand;
        // (safe: next write to uscr/bcastu is separated from these reads
        //  by the syncthreads at the top of the next iteration)
    }

    // ---- mask boost + row max (each thread owns disjoint slots) ----
    float m = -3.402823466e+38f;
    #pragma unroll
    for (int j = 0; j < 8; ++j) {
        int i = tid + j * 256;
        float v = sc[i];
        if (su[i] >= thr) v *= MASKMUL;
        sc[i] = v;
        m = fmaxf(m, v);
    }
    #pragma unroll
    for (int o = 16; o; o >>= 1) m = fmaxf(m, __shfl_xor_sync(0xFFFFFFFFu, m, o));
    if ((tid & 31) == 0) fscr[tid >> 5] = m;
    __syncthreads();
    if (tid < 8) {
        float x = fscr[tid];
        x = fmaxf(x, __shfl_xor_sync(0xFFu, x, 4));
        x = fmaxf(x, __shfl_xor_sync(0xFFu, x, 2));
        x = fmaxf(x, __shfl_xor_sync(0xFFu, x, 1));
        if (tid == 0) bcastf = x;
    }
    __syncthreads();
    const float M = bcastf;

    // ---- exp + sum (normalization folded into the output write) ----
    float sum = 0.f;
    #pragma unroll
    for (int j = 0; j < 8; ++j) {
        int i = tid + j * 256;
        float e = __expf(sc[i] - M);
        sc[i] = e;
        sum += e;
    }
    #pragma unroll
    for (int o = 16; o; o >>= 1) sum += __shfl_xor_sync(0xFFFFFFFFu, sum, o);
    if ((tid & 31) == 0) fscr[tid >> 5] = sum;
    __syncthreads();
    if (tid < 8) {
        float x = fscr[tid];
        x += __shfl_xor_sync(0xFFu, x, 4);
        x += __shfl_xor_sync(0xFFu, x, 2);
        x += __shfl_xor_sync(0xFFu, x, 1);
        if (tid == 0) bcastf = x;
    }
    __syncthreads();
    const float inv = 1.0f / bcastf;

    // ---- out[d] = sum_s p[s] * V[s][d] ----
    const int d4  = tid & 15;   // float4 index into D (d = 4*d4)
    const int grp = tid >> 4;   // 16 groups partition s
    const float4* V4 = (const float4*)(g_V + (size_t)bh * Sq * Dq);
    float4 acc = make_float4(0.f, 0.f, 0.f, 0.f);
    #pragma unroll 8
    for (int s = grp; s < Sq; s += 16) {
        float w = sc[s];
        float4 v = V4[(size_t)s * 16 + d4];
        acc.x = fmaf(w, v.x, acc.x);
        acc.y = fmaf(w, v.y, acc.y);
        acc.z = fmaf(w, v.z, acc.z);
        acc.w = fmaf(w, v.w, acc.w);
    }
    ((float4*)red)[grp * 16 + d4] = acc;
    __syncthreads();
    if (tid < Dq) {
        float o = 0.f;
        #pragma unroll
        for (int g = 0; g < 16; ++g) o += red[g * Dq + tid];
        g_O[((size_t)(b * Sq + t)) * Eq + h * Dq + tid] = o * inv;
    }
}

// ---------------------------------------------------------------------------
// Launch
// ---------------------------------------------------------------------------
extern "C" void kernel_launch(void* const* d_in, const int* in_sizes, int n_in,
                              void* d_out, int out_size)
{
    const float* query = (const float*)d_in[0];
    const float* key   = (const float*)d_in[1];
    const float* value = (const float*)d_in[2];
    const float* Wq    = (const float*)d_in[3];
    const float* bq    = (const float*)d_in[4];
    const float* Wk    = (const float*)d_in[5];
    const float* bk    = (const float*)d_in[6];
    const float* Wv    = (const float*)d_in[7];
    const float* bv    = (const float*)d_in[8];
    const float* Wo    = (const float*)d_in[9];
    const float* bo    = (const float*)d_in[10];
    const float* ts    = (const float*)d_in[11];

    dim3 gProj(Eq / 64, (Bq * Sq) / 64, 3);
    proj_kernel<<<gProj, 256>>>(query, key, value, Wq, bq, Wk, bk, Wv, bv, ts);

    dim3 gAttn(Sq, Bq * Hq);
    attn_kernel<<<gAttn, 256>>>();

    dim3 gOut(Eq / 64, (Bq * Sq) / 64);
    outproj_kernel<<<gOut, 256>>>(Wo, bo, (float*)d_out);
}

// round 2
// speedup vs baseline: 1.2890x; 1.2890x over previous
#include <cuda_runtime.h>

// Problem constants
#define Bq 2
#define Sq 2048
#define Eq 1024
#define Hq 16
#define Dq 64
#define KKq 409           // max(1, int(S*0.2))
#define SCOREMUL 0.15625f // (1/sqrt(64)) / temperature, temperature = 0.8
#define DIAGMUL  1.15f    // 1 + ACH*0.3
#define MASKMUL  1.15f    // 1 + (-DA)*0.3

#define TM 16             // query rows per attention block
#define SCPAD 18          // scT row pad (floats): even (LDS.64 align), stride-18 row walk = 2-way max

// ---------------------------------------------------------------------------
// Scratch (device globals; no allocation allowed in kernel_launch)
// ---------------------------------------------------------------------------
__device__ float g_Q [Bq*Hq*Sq*Dq];   // (b,h,s,d)
__device__ float g_Kt[Bq*Hq*Dq*Sq];   // (b,h,d,s)  transposed, pre-scaled by time_scales
__device__ float g_V [Bq*Hq*Sq*Dq];   // (b,h,s,d)
__device__ float g_O [Bq*Sq*Eq];      // (b,s,e)    attention output before Wo

// ---------------------------------------------------------------------------
// Monotonic float->uint map: a >= b  <=>  fmap(a) >= fmap(b)
// ---------------------------------------------------------------------------
__device__ __forceinline__ unsigned fmap(float f) {
    unsigned u = __float_as_uint(f);
    return (u & 0x80000000u) ? ~u : (u | 0x80000000u);
}

// ---------------------------------------------------------------------------
// Projection GEMM (unchanged from R1): out(mode) = in(mode) @ W(mode) + b
// ---------------------------------------------------------------------------
__global__ __launch_bounds__(256) void proj_kernel(
    const float* __restrict__ qin, const float* __restrict__ kin, const float* __restrict__ vin,
    const float* __restrict__ Wq, const float* __restrict__ bq,
    const float* __restrict__ Wk, const float* __restrict__ bk,
    const float* __restrict__ Wv, const float* __restrict__ bv,
    const float* __restrict__ ts)
{
    const int mode = blockIdx.z;
    const float* A    = (mode == 0) ? qin : (mode == 1) ? kin : vin;
    const float* W    = (mode == 0) ? Wq  : (mode == 1) ? Wk  : Wv;
    const float* bias = (mode == 0) ? bq  : (mode == 1) ? bk  : bv;

    __shared__ float As[16][68];
    __shared__ float Bs[16][64];

    const int tid = threadIdx.x;
    const int tx = tid & 15, ty = tid >> 4;
    const int m0 = blockIdx.y * 64, n0 = blockIdx.x * 64;

    const int aRow = tid >> 2;
    const int aCol = (tid & 3) << 2;
    const int bRow = tid >> 4;
    const int bCol = (tid & 15) << 2;

    const float* Aptr = A + (size_t)(m0 + aRow) * Eq + aCol;
    const float* Wptr = W + (size_t)bRow * Eq + n0 + bCol;

    float acc[4][4];
    #pragma unroll
    for (int i = 0; i < 4; ++i)
        #pragma unroll
        for (int j = 0; j < 4; ++j) acc[i][j] = 0.0f;

    for (int k0 = 0; k0 < Eq; k0 += 16) {
        float4 av  = *(const float4*)(Aptr + k0);
        float4 wv4 = *(const float4*)(Wptr + (size_t)k0 * Eq);
        __syncthreads();
        As[aCol + 0][aRow] = av.x;
        As[aCol + 1][aRow] = av.y;
        As[aCol + 2][aRow] = av.z;
        As[aCol + 3][aRow] = av.w;
        *(float4*)&Bs[bRow][bCol] = wv4;
        __syncthreads();
        #pragma unroll
        for (int k = 0; k < 16; ++k) {
            float a[4], bb[4];
            #pragma unroll
            for (int i = 0; i < 4; ++i) a[i]  = As[k][ty * 4 + i];
            #pragma unroll
            for (int j = 0; j < 4; ++j) bb[j] = Bs[k][tx * 4 + j];
            #pragma unroll
            for (int i = 0; i < 4; ++i)
                #pragma unroll
                for (int j = 0; j < 4; ++j)
                    acc[i][j] = fmaf(a[i], bb[j], acc[i][j]);
        }
    }

    #pragma unroll
    for (int i = 0; i < 4; ++i) {
        int r = m0 + ty * 4 + i;
        int b = r >> 11;
        int s = r & (Sq - 1);
        #pragma unroll
        for (int j = 0; j < 4; ++j) {
            int c = n0 + tx * 4 + j;
            int h = c >> 6, d = c & 63;
            float v = acc[i][j] + bias[c];
            if (mode == 0)
                g_Q[((size_t)(b * Hq + h) * Sq + s) * Dq + d] = v;
            else if (mode == 1)
                g_Kt[((size_t)(b * Hq + h) * Dq + d) * Sq + s] = v * ts[h];
            else
                g_V[((size_t)(b * Hq + h) * Sq + s) * Dq + d] = v;
        }
    }
}

// ---------------------------------------------------------------------------
// Output GEMM (unchanged): d_out = g_O @ Wo + bo
// ---------------------------------------------------------------------------
__global__ __launch_bounds__(256) void outproj_kernel(
    const float* __restrict__ Wo, const float* __restrict__ bo,
    float* __restrict__ out)
{
    __shared__ float As[16][68];
    __shared__ float Bs[16][64];

    const int tid = threadIdx.x;
    const int tx = tid & 15, ty = tid >> 4;
    const int m0 = blockIdx.y * 64, n0 = blockIdx.x * 64;

    const int aRow = tid >> 2;
    const int aCol = (tid & 3) << 2;
    const int bRow = tid >> 4;
    const int bCol = (tid & 15) << 2;

    const float* Aptr = g_O + (size_t)(m0 + aRow) * Eq + aCol;
    const float* Wptr = Wo + (size_t)bRow * Eq + n0 + bCol;

    float acc[4][4];
    #pragma unroll
    for (int i = 0; i < 4; ++i)
        #pragma unroll
        for (int j = 0; j < 4; ++j) acc[i][j] = 0.0f;

    for (int k0 = 0; k0 < Eq; k0 += 16) {
        float4 av  = *(const float4*)(Aptr + k0);
        float4 wv4 = *(const float4*)(Wptr + (size_t)k0 * Eq);
        __syncthreads();
        As[aCol + 0][aRow] = av.x;
        As[aCol + 1][aRow] = av.y;
        As[aCol + 2][aRow] = av.z;
        As[aCol + 3][aRow] = av.w;
        *(float4*)&Bs[bRow][bCol] = wv4;
        __syncthreads();
        #pragma unroll
        for (int k = 0; k < 16; ++k) {
            float a[4], bb[4];
            #pragma unroll
            for (int i = 0; i < 4; ++i) a[i]  = As[k][ty * 4 + i];
            #pragma unroll
            for (int j = 0; j < 4; ++j) bb[j] = Bs[k][tx * 4 + j];
            #pragma unroll
            for (int i = 0; i < 4; ++i)
                #pragma unroll
                for (int j = 0; j < 4; ++j)
                    acc[i][j] = fmaf(a[i], bb[j], acc[i][j]);
        }
    }

    #pragma unroll
    for (int i = 0; i < 4; ++i) {
        int r = m0 + ty * 4 + i;
        #pragma unroll
        for (int j = 0; j < 4; ++j) {
            int c = n0 + tx * 4 + j;
            out[(size_t)r * Eq + c] = acc[i][j] + bo[c];
        }
    }
}

// ---------------------------------------------------------------------------
// Fused attention, tiled: one block = 16 query rows of one (b,h).
// Smem layout (floats):
//   scT  [2048][SCPAD]      scores transposed  (s-major), 147456 B
//   KV   [16384]            K chunk (64d x 256s) / V chunks (2 x 128s x 64d)
//   Qt   [64][16]           Q transposed
//   hist [8][256] (u32)     radix histograms; aliased as red[2][16][64] in PV
//   inv  [16]
// ---------------------------------------------------------------------------
#define OFF_SCT  0
#define OFF_KV   (Sq * SCPAD)            // 36864
#define OFF_QT   (OFF_KV + 16384)        // 53248
#define OFF_HIST (OFF_QT + 1024)         // 54272
#define OFF_INV  (OFF_HIST + 2048)       // 56320
#define SMEM_FLOATS (OFF_INV + 16)       // 56336 -> 225344 B

__global__ __launch_bounds__(256, 1) void attn_kernel()
{
    extern __shared__ float smem[];
    float*    scT  = smem + OFF_SCT;
    float*    KV   = smem + OFF_KV;
    float*    Qt   = smem + OFF_QT;
    unsigned* hist = (unsigned*)(smem + OFF_HIST);
    float*    red  = smem + OFF_HIST;     // alias (PV phase only)
    float*    inv  = smem + OFF_INV;

    const int tid = threadIdx.x;
    const int bh  = blockIdx.y;            // b*H + h
    const int t0  = blockIdx.x * TM;
    const int b   = bh >> 4;
    const int h   = bh & 15;

    const float* Qg  = g_Q  + (size_t)bh * Sq * Dq;
    const float* Ktg = g_Kt + (size_t)bh * Dq * Sq;
    const float* Vg  = g_V  + (size_t)bh * Sq * Dq;

    // ---- load Q tile transposed: Qt[d][r] ----
    for (int i = tid; i < TM * Dq; i += 256) {
        int r = i >> 6, d = i & 63;
        Qt[d * TM + r] = Qg[(size_t)(t0 + r) * Dq + d];
    }

    // ---- QK^T: scores 16 x 2048, chunked 256 s with K staged in smem ----
    const int tx = tid & 63;   // s-quad within chunk
    const int ty = tid >> 6;   // row group (4 rows)
    const float4* Ktg4 = (const float4*)Ktg;

    for (int c = 0; c < 8; ++c) {
        const int s0 = c * 256;
        __syncthreads();   // previous chunk compute done (and Qt ready on c==0)
        // stage K chunk: KV as Ks[64][256]
        for (int i = tid; i < 4096; i += 256) {
            int d = i >> 6, sq = i & 63;
            ((float4*)KV)[i] = Ktg4[(size_t)d * (Sq / 4) + (s0 >> 2) + sq];
        }
        __syncthreads();

        float acc[4][4];
        #pragma unroll
        for (int i = 0; i < 4; ++i)
            #pragma unroll
            for (int j = 0; j < 4; ++j) acc[i][j] = 0.0f;

        #pragma unroll 8
        for (int d = 0; d < Dq; ++d) {
            float4 a = *(const float4*)(Qt + d * TM + ty * 4);
            float4 bb = *(const float4*)(KV + d * 256 + tx * 4);
            acc[0][0] = fmaf(a.x, bb.x, acc[0][0]); acc[0][1] = fmaf(a.x, bb.y, acc[0][1]);
            acc[0][2] = fmaf(a.x, bb.z, acc[0][2]); acc[0][3] = fmaf(a.x, bb.w, acc[0][3]);
            acc[1][0] = fmaf(a.y, bb.x, acc[1][0]); acc[1][1] = fmaf(a.y, bb.y, acc[1][1]);
            acc[1][2] = fmaf(a.y, bb.z, acc[1][2]); acc[1][3] = fmaf(a.y, bb.w, acc[1][3]);
            acc[2][0] = fmaf(a.z, bb.x, acc[2][0]); acc[2][1] = fmaf(a.z, bb.y, acc[2][1]);
            acc[2][2] = fmaf(a.z, bb.z, acc[2][2]); acc[2][3] = fmaf(a.z, bb.w, acc[2][3]);
            acc[3][0] = fmaf(a.w, bb.x, acc[3][0]); acc[3][1] = fmaf(a.w, bb.y, acc[3][1]);
            acc[3][2] = fmaf(a.w, bb.z, acc[3][2]); acc[3][3] = fmaf(a.w, bb.w, acc[3][3]);
        }

        #pragma unroll
        for (int i = 0; i < 4; ++i) {
            int r = ty * 4 + i;
            int tg = t0 + r;
            #pragma unroll
            for (int j = 0; j < 4; ++j) {
                int s = s0 + tx * 4 + j;
                float v = acc[i][j] * SCOREMUL;
                if (s == tg) v *= DIAGMUL;
                scT[s * SCPAD + r] = v;
            }
        }
    }
    __syncthreads();

    // ---- per-row: exact top-k threshold (radix select) + softmax ----
    {
        const int warp = tid >> 5, lane = tid & 31;
        unsigned* hw = hist + warp * 256;

        for (int rr = 0; rr < 2; ++rr) {
            const int r = warp * 2 + rr;
            unsigned thrp = 0;
            int kneed = KKq;

            for (int shift = 24; shift >= 0; shift -= 8) {
                #pragma unroll
                for (int j = 0; j < 8; ++j) hw[lane + j * 32] = 0;
                __syncwarp();
                for (int i = lane; i < Sq; i += 32) {
                    unsigned u = fmap(scT[i * SCPAD + r]);
                    bool ok = (shift == 24) || (((u ^ thrp) >> (shift + 8)) == 0);
                    if (ok) atomicAdd(&hw[(u >> shift) & 255], 1u);
                }
                __syncwarp();
                // descending scan: lane 0 owns highest bins [248..255]
                const int b0 = (31 - lane) * 8;
                unsigned cb[8], cl = 0;
                #pragma unroll
                for (int j = 0; j < 8; ++j) { cb[j] = hw[b0 + j]; cl += cb[j]; }
                unsigned S = cl;
                #pragma unroll
                for (int o = 1; o < 32; o <<= 1) {
                    unsigned x = __shfl_up_sync(0xFFFFFFFFu, S, o);
                    if (lane >= o) S += x;
                }
                unsigned excl = S - cl;
                bool has = (excl < (unsigned)kneed) && ((unsigned)kneed <= S);
                unsigned bal = __ballot_sync(0xFFFFFFFFu, has);
                int src = __ffs(bal) - 1;
                int bsel = 0, nk = 0;
                if (lane == src) {
                    int rem = kneed - (int)excl;
                    #pragma unroll
                    for (int j = 7; j >= 0; --j) {
                        int cnt = (int)cb[j];
                        if (rem <= cnt) { bsel = b0 + j; nk = rem; break; }
                        rem -= cnt;
                    }
                }
                bsel = __shfl_sync(0xFFFFFFFFu, bsel, src);
                nk   = __shfl_sync(0xFFFFFFFFu, nk, src);
                thrp |= ((unsigned)bsel) << shift;
                kneed = nk;
                __syncwarp();
            }

            // boost + row max
            float mx = -3.402823466e+38f;
            for (int i = lane; i < Sq; i += 32) {
                float v = scT[i * SCPAD + r];
                if (fmap(v) >= thrp) v *= MASKMUL;
                scT[i * SCPAD + r] = v;
                mx = fmaxf(mx, v);
            }
            #pragma unroll
            for (int o = 16; o; o >>= 1) mx = fmaxf(mx, __shfl_xor_sync(0xFFFFFFFFu, mx, o));

            // exp + sum
            float sum = 0.0f;
            for (int i = lane; i < Sq; i += 32) {
                float e = __expf(scT[i * SCPAD + r] - mx);
                scT[i * SCPAD + r] = e;
                sum += e;
            }
            #pragma unroll
            for (int o = 16; o; o >>= 1) sum += __shfl_xor_sync(0xFFFFFFFFu, sum, o);
            if (lane == 0) inv[r] = 1.0f / sum;
        }
    }
    __syncthreads();

    // ---- P @ V: out 16 x 64, V staged 2 x 128s x 64d per iteration ----
    {
        const int g  = tid >> 7;          // s-half: 0 -> [0,1024), 1 -> [1024,2048)
        const int rm = tid & 127;
        const int dx = rm & 15;           // d quad
        const int ry = rm >> 4;           // row pair index (rows ry*2, ry*2+1)
        const float4* Vg4 = (const float4*)Vg;

        float4 acc0 = make_float4(0.f, 0.f, 0.f, 0.f);
        float4 acc1 = make_float4(0.f, 0.f, 0.f, 0.f);

        for (int it = 0; it < 8; ++it) {
            __syncthreads();
            // stage: KV[0..2047] f4 = half-A chunk (128s x 64d), [2048..4095] = half-B
            const int sA = it * 128;
            const int sB = 1024 + it * 128;
            for (int i = tid; i < 4096; i += 256) {
                ((float4*)KV)[i] = (i < 2048) ? Vg4[(size_t)sA * 16 + i]
                                              : Vg4[(size_t)sB * 16 + (i - 2048)];
            }
            __syncthreads();

            const float* vbase = KV + g * 8192;
            const int sbase = g * 1024 + it * 128;
            #pragma unroll 8
            for (int ls = 0; ls < 128; ++ls) {
                float2 w = *(const float2*)(scT + (sbase + ls) * SCPAD + ry * 2);
                float4 v = *(const float4*)(vbase + ls * 64 + dx * 4);
                acc0.x = fmaf(w.x, v.x, acc0.x); acc0.y = fmaf(w.x, v.y, acc0.y);
                acc0.z = fmaf(w.x, v.z, acc0.z); acc0.w = fmaf(w.x, v.w, acc0.w);
                acc1.x = fmaf(w.y, v.x, acc1.x); acc1.y = fmaf(w.y, v.y, acc1.y);
                acc1.z = fmaf(w.y, v.z, acc1.z); acc1.w = fmaf(w.y, v.w, acc1.w);
            }
        }
        __syncthreads();   // topk/hist done long ago; ensure all PV reads of scT finished before red alias writes? (red aliases hist, not scT) -- still need all threads past staging loops
        // write partials: red[g][r][d]
        *(float4*)(red + ((g * TM + ry * 2 + 0) * Dq + dx * 4)) = acc0;
        *(float4*)(red + ((g * TM + ry * 2 + 1) * Dq + dx * 4)) = acc1;
    }
    __syncthreads();

    // ---- reduce partials, normalize, write g_O ----
    for (int i = tid; i < TM * Dq; i += 256) {
        int r = i >> 6, d = i & 63;
        float o = (red[r * Dq + d] + red[TM * Dq + r * Dq + d]) * inv[r];
        g_O[((size_t)(b * Sq + t0 + r)) * Eq + h * Dq + d] = o;
    }
}

// ---------------------------------------------------------------------------
// Launch
// ---------------------------------------------------------------------------
extern "C" void kernel_launch(void* const* d_in, const int* in_sizes, int n_in,
                              void* d_out, int out_size)
{
    const float* query = (const float*)d_in[0];
    const float* key   = (const float*)d_in[1];
    const float* value = (const float*)d_in[2];
    const float* Wq    = (const float*)d_in[3];
    const float* bq    = (const float*)d_in[4];
    const float* Wk    = (const float*)d_in[5];
    const float* bk    = (const float*)d_in[6];
    const float* Wv    = (const float*)d_in[7];
    const float* bv    = (const float*)d_in[8];
    const float* Wo    = (const float*)d_in[9];
    const float* bo    = (const float*)d_in[10];
    const float* ts    = (const float*)d_in[11];

    static int smem_set = 0;
    if (!smem_set) {
        cudaFuncSetAttribute(attn_kernel, cudaFuncAttributeMaxDynamicSharedMemorySize,
                             SMEM_FLOATS * 4);
        smem_set = 1;
    }

    dim3 gProj(Eq / 64, (Bq * Sq) / 64, 3);
    proj_kernel<<<gProj, 256>>>(query, key, value, Wq, bq, Wk, bk, Wv, bv, ts);

    dim3 gAttn(Sq / TM, Bq * Hq);
    attn_kernel<<<gAttn, 256, SMEM_FLOATS * 4>>>();

    dim3 gOut(Eq / 64, (Bq * Sq) / 64);
    outproj_kernel<<<gOut, 256>>>(Wo, bo, (float*)d_out);
}

// round 4
// speedup vs baseline: 1.5385x; 1.1936x over previous
#include <cuda_runtime.h>
#include <cstdint>

// Problem constants
#define Bq 2
#define Sq 2048
#define Eq 1024
#define Hq 16
#define Dq 64
#define KKq 409           // max(1, int(S*0.2))
#define SCOREMUL 0.15625f // (1/sqrt(64)) / temperature, temperature = 0.8
#define DIAGMUL  1.15f    // 1 + ACH*0.3
#define MASKMUL  1.15f    // 1 + (-DA)*0.3

#define TM 16             // query rows per attention block
#define SCPAD 18          // scT row pad

// ---------------------------------------------------------------------------
// Scratch (device globals)
// ---------------------------------------------------------------------------
__device__ float g_Q [Bq*Hq*Sq*Dq];   // (b,h,s,d)
__device__ float g_Kt[Bq*Hq*Dq*Sq];   // (b,h,d,s)  transposed, pre-scaled by time_scales
__device__ float g_V [Bq*Hq*Sq*Dq];   // (b,h,s,d)
__device__ float g_O [Bq*Sq*Eq];      // (b,s,e)
__device__ float g_Wt[4*Eq*Eq];       // Wq^T, Wk^T, Wv^T, Wo^T (out-feature rows, K contiguous)

// ---------------------------------------------------------------------------
// bf16x2 helpers
// ---------------------------------------------------------------------------
__device__ __forceinline__ uint32_t bfpack(float lo, float hi) {
    uint32_t r;
    asm("cvt.rn.bf16x2.f32 %0, %1, %2;" : "=r"(r) : "f"(hi), "f"(lo));
    return r;   // low 16 bits = lo, high 16 bits = hi
}
__device__ __forceinline__ float bflowf(uint32_t p)  { return __uint_as_float(p << 16); }
__device__ __forceinline__ float bfhighf(uint32_t p) { return __uint_as_float(p & 0xFFFF0000u); }

__device__ __forceinline__ void mma_bf16(float* d, const uint32_t* a, uint32_t b0, uint32_t b1) {
    asm volatile(
        "mma.sync.aligned.m16n8k16.row.col.f32.bf16.bf16.f32 "
        "{%0,%1,%2,%3}, {%4,%5,%6,%7}, {%8,%9}, {%0,%1,%2,%3};"
        : "+f"(d[0]), "+f"(d[1]), "+f"(d[2]), "+f"(d[3])
        : "r"(a[0]), "r"(a[1]), "r"(a[2]), "r"(a[3]), "r"(b0), "r"(b1));
}

// ---------------------------------------------------------------------------
// Monotonic float->uint map
// ---------------------------------------------------------------------------
__device__ __forceinline__ unsigned fmap(float f) {
    unsigned u = __float_as_uint(f);
    return (u & 0x80000000u) ? ~u : (u | 0x80000000u);
}

// ---------------------------------------------------------------------------
// Weight transpose: g_Wt[z] = W(z)^T
// ---------------------------------------------------------------------------
__global__ void wtrans_kernel(const float* __restrict__ Wq, const float* __restrict__ Wk,
                              const float* __restrict__ Wv, const float* __restrict__ Wo)
{
    __shared__ float t[32][33];
    const int z = blockIdx.z;
    const float* W = (z == 0) ? Wq : (z == 1) ? Wk : (z == 2) ? Wv : Wo;
    float* out = g_Wt + (size_t)z * Eq * Eq;
    const int x0 = blockIdx.x * 32, y0 = blockIdx.y * 32;
    const int tx = threadIdx.x, ty = threadIdx.y;
    #pragma unroll
    for (int i = 0; i < 32; i += 8)
        t[ty + i][tx] = W[(size_t)(y0 + ty + i) * Eq + x0 + tx];
    __syncthreads();
    #pragma unroll
    for (int i = 0; i < 32; i += 8)
        out[(size_t)(x0 + ty + i) * Eq + y0 + tx] = t[tx][ty + i];
}

// ---------------------------------------------------------------------------
// bf16x3 mma.sync GEMM: C[m][n] = sum_k A[m][k] * Bt[n][k]  (+ mode epilogue)
//   mode 0: A=query, Bt=Wq^T -> g_Q  (b,h,s,d), +bq
//   mode 1: A=Wk^T,  Bt=key  -> g_Kt (b,h,d,s), (+bk)*ts[h]
//   mode 2: A=value, Bt=Wv^T -> g_V  (b,h,s,d), +bv
//   mode 3: A=g_O,   Bt=Wo^T -> Cout row-major, +bo
// Block tile 128x128, k-chunk 32, 8 warps (4m x 2n), warp tile 32x64.
// smem: hi/lo bf16x2 arrays, row stride 20 u32 (conflict-free frag loads).
// ---------------------------------------------------------------------------
#define SROW 20

__global__ __launch_bounds__(256) void gemm_mma_kernel(
    const float* __restrict__ A, const float* __restrict__ Bt,
    const float* __restrict__ bias, const float* __restrict__ ts,
    int mode, float* __restrict__ Cout)
{
    __shared__ uint32_t sb[4 * 128 * SROW];   // Ahi, Alo, Bhi, Blo : 40KB
    uint32_t* Ahi = sb;
    uint32_t* Alo = sb + 128 * SROW;
    uint32_t* Bhi = sb + 2 * 128 * SROW;
    uint32_t* Blo = sb + 3 * 128 * SROW;

    const int tid  = threadIdx.x;
    const int wid  = tid >> 5, lane = tid & 31;
    const int gid  = lane >> 2, tig = lane & 3;
    const int wm   = wid & 3,  wn  = wid >> 2;
    const int m0   = blockIdx.y * 128, n0 = blockIdx.x * 128;

    // loader mapping: 4 float4 per thread per operand per chunk
    const float4* pa[4];
    const float4* pb[4];
    int so[4];
    #pragma unroll
    for (int j = 0; j < 4; ++j) {
        int f4  = tid + j * 256;      // 0..1023
        int row = f4 >> 3;            // 0..127
        int cq  = f4 & 7;             // float4 index within 32-k row
        pa[j] = (const float4*)(A  + (size_t)(m0 + row) * Eq) + cq;
        pb[j] = (const float4*)(Bt + (size_t)(n0 + row) * Eq) + cq;
        so[j] = row * SROW + cq * 2;
    }

    float4 ra[4], rb[4];
    #pragma unroll
    for (int j = 0; j < 4; ++j) { ra[j] = pa[j][0]; rb[j] = pb[j][0]; }

    float acc[2][8][4];
    #pragma unroll
    for (int mt = 0; mt < 2; ++mt)
        #pragma unroll
        for (int nt = 0; nt < 8; ++nt)
            #pragma unroll
            for (int c = 0; c < 4; ++c) acc[mt][nt][c] = 0.0f;

    for (int kc = 0; kc < 32; ++kc) {
        __syncthreads();   // previous chunk's compute finished
        #pragma unroll
        for (int j = 0; j < 4; ++j) {
            uint32_t h0 = bfpack(ra[j].x, ra[j].y);
            uint32_t h1 = bfpack(ra[j].z, ra[j].w);
            Ahi[so[j]]     = h0;
            Ahi[so[j] + 1] = h1;
            Alo[so[j]]     = bfpack(ra[j].x - bflowf(h0), ra[j].y - bfhighf(h0));
            Alo[so[j] + 1] = bfpack(ra[j].z - bflowf(h1), ra[j].w - bfhighf(h1));
            uint32_t g0 = bfpack(rb[j].x, rb[j].y);
            uint32_t g1 = bfpack(rb[j].z, rb[j].w);
            Bhi[so[j]]     = g0;
            Bhi[so[j] + 1] = g1;
            Blo[so[j]]     = bfpack(rb[j].x - bflowf(g0), rb[j].y - bfhighf(g0));
            Blo[so[j] + 1] = bfpack(rb[j].z - bflowf(g1), rb[j].w - bfhighf(g1));
        }
        __syncthreads();

        if (kc < 31) {
            #pragma unroll
            for (int j = 0; j < 4; ++j) {
                ra[j] = pa[j][(kc + 1) * 8];
                rb[j] = pb[j][(kc + 1) * 8];
            }
        }

        #pragma unroll
        for (int ks = 0; ks < 2; ++ks) {
            const int kb = ks * 8;
            uint32_t ah[2][4], al[2][4];
            #pragma unroll
            for (int mt = 0; mt < 2; ++mt) {
                const int r0 = wm * 32 + mt * 16 + gid;
                ah[mt][0] = Ahi[r0 * SROW + kb + tig];
                ah[mt][1] = Ahi[(r0 + 8) * SROW + kb + tig];
                ah[mt][2] = Ahi[r0 * SROW + kb + tig + 4];
                ah[mt][3] = Ahi[(r0 + 8) * SROW + kb + tig + 4];
                al[mt][0] = Alo[r0 * SROW + kb + tig];
                al[mt][1] = Alo[(r0 + 8) * SROW + kb + tig];
                al[mt][2] = Alo[r0 * SROW + kb + tig + 4];
                al[mt][3] = Alo[(r0 + 8) * SROW + kb + tig + 4];
            }
            #pragma unroll
            for (int nt = 0; nt < 8; ++nt) {
                const int n = wn * 64 + nt * 8 + gid;
                uint32_t bh0 = Bhi[n * SROW + kb + tig];
                uint32_t bh1 = Bhi[n * SROW + kb + tig + 4];
                uint32_t bl0 = Blo[n * SROW + kb + tig];
                uint32_t bl1 = Blo[n * SROW + kb + tig + 4];
                #pragma unroll
                for (int mt = 0; mt < 2; ++mt) {
                    mma_bf16(acc[mt][nt], ah[mt], bh0, bh1);
                    mma_bf16(acc[mt][nt], ah[mt], bl0, bl1);
                    mma_bf16(acc[mt][nt], al[mt], bh0, bh1);
                }
            }
        }
    }

    // ---- epilogue ----
    #pragma unroll
    for (int mt = 0; mt < 2; ++mt) {
        const int row = m0 + wm * 32 + mt * 16 + gid;
        #pragma unroll
        for (int nt = 0; nt < 8; ++nt) {
            const int col = n0 + wn * 64 + nt * 8 + 2 * tig;
            const float* d = acc[mt][nt];
            if (mode == 3) {
                float2 bv = *(const float2*)(bias + col);
                *(float2*)(Cout + (size_t)row * Eq + col) =
                    make_float2(d[0] + bv.x, d[1] + bv.y);
                *(float2*)(Cout + (size_t)(row + 8) * Eq + col) =
                    make_float2(d[2] + bv.x, d[3] + bv.y);
            } else if (mode == 1) {
                // row = out feature i, col = sample s
                const int s  = col;
                const int bb = s >> 11, sl = s & (Sq - 1);
                {
                    const int i = row, h = i >> 6, dd = i & 63;
                    const float fb = bias[i], tv = ts[h];
                    *(float2*)(g_Kt + ((size_t)(bb * Hq + h) * Dq + dd) * Sq + sl) =
                        make_float2((d[0] + fb) * tv, (d[1] + fb) * tv);
                }
                {
                    const int i = row + 8, h = i >> 6, dd = i & 63;
                    const float fb = bias[i], tv = ts[h];
                    *(float2*)(g_Kt + ((size_t)(bb * Hq + h) * Dq + dd) * Sq + sl) =
                        make_float2((d[2] + fb) * tv, (d[3] + fb) * tv);
                }
            } else {
                // row = sample, col = feature
                const int bb = row >> 11, s = row & (Sq - 1);
                const int h = col >> 6, dd = col & 63;
                float* base = (mode == 0) ? g_Q : g_V;
                float2 bv = *(const float2*)(bias + col);
                float* dst = base + ((size_t)(bb * Hq + h) * Sq + s) * Dq + dd;
                *(float2*)(dst)           = make_float2(d[0] + bv.x, d[1] + bv.y);
                *(float2*)(dst + 8 * Dq)  = make_float2(d[2] + bv.x, d[3] + bv.y);
            }
        }
    }
}

// ---------------------------------------------------------------------------
// Fused attention (unchanged from R2): one block = 16 query rows of one (b,h).
// ---------------------------------------------------------------------------
#define OFF_SCT  0
#define OFF_KV   (Sq * SCPAD)
#define OFF_QT   (OFF_KV + 16384)
#define OFF_HIST (OFF_QT + 1024)
#define OFF_INV  (OFF_HIST + 2048)
#define SMEM_FLOATS (OFF_INV + 16)

__global__ __launch_bounds__(256, 1) void attn_kernel()
{
    extern __shared__ float smem[];
    float*    scT  = smem + OFF_SCT;
    float*    KV   = smem + OFF_KV;
    float*    Qt   = smem + OFF_QT;
    unsigned* hist = (unsigned*)(smem + OFF_HIST);
    float*    red  = smem + OFF_HIST;
    float*    inv  = smem + OFF_INV;

    const int tid = threadIdx.x;
    const int bh  = blockIdx.y;
    const int t0  = blockIdx.x * TM;
    const int b   = bh >> 4;
    const int h   = bh & 15;

    const float* Qg  = g_Q  + (size_t)bh * Sq * Dq;
    const float* Ktg = g_Kt + (size_t)bh * Dq * Sq;
    const float* Vg  = g_V  + (size_t)bh * Sq * Dq;

    for (int i = tid; i < TM * Dq; i += 256) {
        int r = i >> 6, d = i & 63;
        Qt[d * TM + r] = Qg[(size_t)(t0 + r) * Dq + d];
    }

    const int tx = tid & 63;
    const int ty = tid >> 6;
    const float4* Ktg4 = (const float4*)Ktg;

    for (int c = 0; c < 8; ++c) {
        const int s0 = c * 256;
        __syncthreads();
        for (int i = tid; i < 4096; i += 256) {
            int d = i >> 6, sq = i & 63;
            ((float4*)KV)[i] = Ktg4[(size_t)d * (Sq / 4) + (s0 >> 2) + sq];
        }
        __syncthreads();

        float acc[4][4];
        #pragma unroll
        for (int i = 0; i < 4; ++i)
            #pragma unroll
            for (int j = 0; j < 4; ++j) acc[i][j] = 0.0f;

        #pragma unroll 8
        for (int d = 0; d < Dq; ++d) {
            float4 a = *(const float4*)(Qt + d * TM + ty * 4);
            float4 bb = *(const float4*)(KV + d * 256 + tx * 4);
            acc[0][0] = fmaf(a.x, bb.x, acc[0][0]); acc[0][1] = fmaf(a.x, bb.y, acc[0][1]);
            acc[0][2] = fmaf(a.x, bb.z, acc[0][2]); acc[0][3] = fmaf(a.x, bb.w, acc[0][3]);
            acc[1][0] = fmaf(a.y, bb.x, acc[1][0]); acc[1][1] = fmaf(a.y, bb.y, acc[1][1]);
            acc[1][2] = fmaf(a.y, bb.z, acc[1][2]); acc[1][3] = fmaf(a.y, bb.w, acc[1][3]);
            acc[2][0] = fmaf(a.z, bb.x, acc[2][0]); acc[2][1] = fmaf(a.z, bb.y, acc[2][1]);
            acc[2][2] = fmaf(a.z, bb.z, acc[2][2]); acc[2][3] = fmaf(a.z, bb.w, acc[2][3]);
            acc[3][0] = fmaf(a.w, bb.x, acc[3][0]); acc[3][1] = fmaf(a.w, bb.y, acc[3][1]);
            acc[3][2] = fmaf(a.w, bb.z, acc[3][2]); acc[3][3] = fmaf(a.w, bb.w, acc[3][3]);
        }

        #pragma unroll
        for (int i = 0; i < 4; ++i) {
            int r = ty * 4 + i;
            int tg = t0 + r;
            #pragma unroll
            for (int j = 0; j < 4; ++j) {
                int s = s0 + tx * 4 + j;
                float v = acc[i][j] * SCOREMUL;
                if (s == tg) v *= DIAGMUL;
                scT[s * SCPAD + r] = v;
            }
        }
    }
    __syncthreads();

    {
        const int warp = tid >> 5, lane = tid & 31;
        unsigned* hw = hist + warp * 256;

        for (int rr = 0; rr < 2; ++rr) {
            const int r = warp * 2 + rr;
            unsigned thrp = 0;
            int kneed = KKq;

            for (int shift = 24; shift >= 0; shift -= 8) {
                #pragma unroll
                for (int j = 0; j < 8; ++j) hw[lane + j * 32] = 0;
                __syncwarp();
                for (int i = lane; i < Sq; i += 32) {
                    unsigned u = fmap(scT[i * SCPAD + r]);
                    bool ok = (shift == 24) || (((u ^ thrp) >> (shift + 8)) == 0);
                    if (ok) atomicAdd(&hw[(u >> shift) & 255], 1u);
                }
                __syncwarp();
                const int b0 = (31 - lane) * 8;
                unsigned cb[8], cl = 0;
                #pragma unroll
                for (int j = 0; j < 8; ++j) { cb[j] = hw[b0 + j]; cl += cb[j]; }
                unsigned S = cl;
                #pragma unroll
                for (int o = 1; o < 32; o <<= 1) {
                    unsigned x = __shfl_up_sync(0xFFFFFFFFu, S, o);
                    if (lane >= o) S += x;
                }
                unsigned excl = S - cl;
                bool has = (excl < (unsigned)kneed) && ((unsigned)kneed <= S);
                unsigned bal = __ballot_sync(0xFFFFFFFFu, has);
                int src = __ffs(bal) - 1;
                int bsel = 0, nk = 0;
                if (lane == src) {
                    int rem = kneed - (int)excl;
                    #pragma unroll
                    for (int j = 7; j >= 0; --j) {
                        int cnt = (int)cb[j];
                        if (rem <= cnt) { bsel = b0 + j; nk = rem; break; }
                        rem -= cnt;
                    }
                }
                bsel = __shfl_sync(0xFFFFFFFFu, bsel, src);
                nk   = __shfl_sync(0xFFFFFFFFu, nk, src);
                thrp |= ((unsigned)bsel) << shift;
                kneed = nk;
                __syncwarp();
            }

            float mx = -3.402823466e+38f;
            for (int i = lane; i < Sq; i += 32) {
                float v = scT[i * SCPAD + r];
                if (fmap(v) >= thrp) v *= MASKMUL;
                scT[i * SCPAD + r] = v;
                mx = fmaxf(mx, v);
            }
            #pragma unroll
            for (int o = 16; o; o >>= 1) mx = fmaxf(mx, __shfl_xor_sync(0xFFFFFFFFu, mx, o));

            float sum = 0.0f;
            for (int i = lane; i < Sq; i += 32) {
                float e = __expf(scT[i * SCPAD + r] - mx);
                scT[i * SCPAD + r] = e;
                sum += e;
            }
            #pragma unroll
            for (int o = 16; o; o >>= 1) sum += __shfl_xor_sync(0xFFFFFFFFu, sum, o);
            if (lane == 0) inv[r] = 1.0f / sum;
        }
    }
    __syncthreads();

    {
        const int g  = tid >> 7;
        const int rm = tid & 127;
        const int dx = rm & 15;
        const int ry = rm >> 4;
        const float4* Vg4 = (const float4*)Vg;

        float4 acc0 = make_float4(0.f, 0.f, 0.f, 0.f);
        float4 acc1 = make_float4(0.f, 0.f, 0.f, 0.f);

        for (int it = 0; it < 8; ++it) {
            __syncthreads();
            const int sA = it * 128;
            const int sB = 1024 + it * 128;
            for (int i = tid; i < 4096; i += 256) {
                ((float4*)KV)[i] = (i < 2048) ? Vg4[(size_t)sA * 16 + i]
                                              : Vg4[(size_t)sB * 16 + (i - 2048)];
            }
            __syncthreads();

            const float* vbase = KV + g * 8192;
            const int sbase = g * 1024 + it * 128;
            #pragma unroll 8
            for (int ls = 0; ls < 128; ++ls) {
                float2 w = *(const float2*)(scT + (sbase + ls) * SCPAD + ry * 2);
                float4 v = *(const float4*)(vbase + ls * 64 + dx * 4);
                acc0.x = fmaf(w.x, v.x, acc0.x); acc0.y = fmaf(w.x, v.y, acc0.y);
                acc0.z = fmaf(w.x, v.z, acc0.z); acc0.w = fmaf(w.x, v.w, acc0.w);
                acc1.x = fmaf(w.y, v.x, acc1.x); acc1.y = fmaf(w.y, v.y, acc1.y);
                acc1.z = fmaf(w.y, v.z, acc1.z); acc1.w = fmaf(w.y, v.w, acc1.w);
            }
        }
        __syncthreads();
        *(float4*)(red + ((g * TM + ry * 2 + 0) * Dq + dx * 4)) = acc0;
        *(float4*)(red + ((g * TM + ry * 2 + 1) * Dq + dx * 4)) = acc1;
    }
    __syncthreads();

    for (int i = tid; i < TM * Dq; i += 256) {
        int r = i >> 6, d = i & 63;
        float o = (red[r * Dq + d] + red[TM * Dq + r * Dq + d]) * inv[r];
        g_O[((size_t)(b * Sq + t0 + r)) * Eq + h * Dq + d] = o;
    }
}

// ---------------------------------------------------------------------------
// Launch
// ---------------------------------------------------------------------------
extern "C" void kernel_launch(void* const* d_in, const int* in_sizes, int n_in,
                              void* d_out, int out_size)
{
    const float* query = (const float*)d_in[0];
    const float* key   = (const float*)d_in[1];
    const float* value = (const float*)d_in[2];
    const float* Wq    = (const float*)d_in[3];
    const float* bq    = (const float*)d_in[4];
    const float* Wk    = (const float*)d_in[5];
    const float* bk    = (const float*)d_in[6];
    const float* Wv    = (const float*)d_in[7];
    const float* bv    = (const float*)d_in[8];
    const float* Wo    = (const float*)d_in[9];
    const float* bo    = (const float*)d_in[10];
    const float* ts    = (const float*)d_in[11];

    static int attr_set = 0;
    if (!attr_set) {
        cudaFuncSetAttribute(attn_kernel, cudaFuncAttributeMaxDynamicSharedMemorySize,
                             SMEM_FLOATS * 4);
        attr_set = 1;
    }

    // weight transposes
    dim3 gT(Eq / 32, Eq / 32, 4);
    wtrans_kernel<<<gT, dim3(32, 8)>>>(Wq, Wk, Wv, Wo);

    float* wt; cudaGetSymbolAddress((void**)&wt, g_Wt);
    float* gO; cudaGetSymbolAddress((void**)&gO, g_O);

    dim3 gA(Eq / 128, (Bq * Sq) / 128);        // modes 0, 2, 3
    dim3 gK((Bq * Sq) / 128, Eq / 128);        // mode 1

    gemm_mma_kernel<<<gA, 256>>>(query, wt + 0 * (size_t)Eq * Eq, bq, ts, 0, nullptr);
    gemm_mma_kernel<<<gK, 256>>>(wt + 1 * (size_t)Eq * Eq, key,   bk, ts, 1, nullptr);
    gemm_mma_kernel<<<gA, 256>>>(value, wt + 2 * (size_t)Eq * Eq, bv, ts, 2, nullptr);

    dim3 gAttn(Sq / TM, Bq * Hq);
    attn_kernel<<<gAttn, 256, SMEM_FLOATS * 4>>>();

    gemm_mma_kernel<<<gA, 256>>>(gO, wt + 3 * (size_t)Eq * Eq, bo, ts, 3, (float*)d_out);
}